// round 15
// baseline (speedup 1.0000x reference)
#include <cuda_runtime.h>
#include <cstdint>

#define SEQ   2048
#define BATCH 64
#define MROWS (SEQ * BATCH)   // 131072
#define EPSBN 1e-5f

// ---------------- scratch (device globals; no allocations allowed) ----------
__device__ float g_bufA[33554432];    // [MROWS][<=256]
__device__ float g_bufB[33554432];    // [MROWS][<=256]
__device__ float g_xw[134217728];     // [2][MROWS][<=512]
__device__ float g_part [16384];      // [128 chains][<=128]
__device__ float g_part2[16384];
__device__ float g_scale[256];
__device__ float g_shift[256];

// ---------------- f32x2 helpers ---------------------------------------------
__device__ __forceinline__ unsigned long long pk2(float x, float y) {
    unsigned long long r;
    asm("mov.b64 %0, {%1,%2};" : "=l"(r) : "f"(x), "f"(y));
    return r;
}
__device__ __forceinline__ void fma2(unsigned long long& d,
                                     unsigned long long a, unsigned long long b) {
    asm("fma.rn.f32x2 %0, %1, %2, %0;" : "+l"(d) : "l"(a), "l"(b));
}
__device__ __forceinline__ float2 up2(unsigned long long v) {
    float2 f;
    asm("mov.b64 {%0,%1}, %2;" : "=f"(f.x), "=f"(f.y) : "l"(v));
    return f;
}
__device__ __forceinline__ float fast_sig(float x) {
    return __fdividef(1.f, 1.f + __expf(-x));
}
__device__ __forceinline__ float fast_tanh(float x) {
    float e = __expf(-2.f * x);
    return __fdividef(1.f - e, 1.f + e);
}

// ---------------- padding kernel (also zeroes stats scratch; deterministic) --
__global__ void pad_zero(float* __restrict__ p, int n) {
    int i = blockIdx.x * blockDim.x + threadIdx.x;
    if (i < n) p[i] = 0.f;
}

// ---------------- layer-0 GEMM (N=64, K=7): 64x64 tile ----------------------
__global__ void __launch_bounds__(256)
gemm_small(const float* __restrict__ X, const float* __restrict__ W,
           const float* __restrict__ bih, const float* __restrict__ bhh,
           float* __restrict__ OUT, int K, int N) {
    __shared__ __align__(16) float As[8][64];
    __shared__ __align__(16) float Bs[8][64];
    const int tid = threadIdx.x;
    const int d = blockIdx.z;
    const float* Wd = W + (size_t)d * N * K;
    const float* bi = bih + d * N;
    const float* bh = bhh + d * N;
    float* outd = OUT + (size_t)d * MROWS * N;
    const int m0 = blockIdx.x * 64, n0 = blockIdx.y * 64;
    const int tx = tid & 15, ty = tid >> 4;
    unsigned long long acc2[4][2] = {};
    for (int k0 = 0; k0 < K; k0 += 8) {
#pragma unroll
        for (int it = 0; it < 2; it++) {
            int idx = tid + it * 256;
            int r = idx >> 3, c = idx & 7;
            float xv = 0.f;
            if (k0 + c < K) {
                int m = m0 + r;
                int b = m & 63, s = m >> 6;
                xv = X[((size_t)b * SEQ + s) * 7 + k0 + c];
            }
            As[c][r] = xv;
        }
#pragma unroll
        for (int it = 0; it < 2; it++) {
            int idx = tid + it * 256;
            int n = idx & 63, c = idx >> 6;
            Bs[c][n] = (k0 + c < K) ? Wd[(size_t)(n0 + n) * K + k0 + c] : 0.f;
        }
        __syncthreads();
#pragma unroll
        for (int k = 0; k < 8; k++) {
            float4 av = *(const float4*)&As[k][ty * 4];
            ulonglong2 bv = *(const ulonglong2*)&Bs[k][tx * 4];
            unsigned long long a0 = pk2(av.x, av.x);
            unsigned long long a1 = pk2(av.y, av.y);
            unsigned long long a2 = pk2(av.z, av.z);
            unsigned long long a3 = pk2(av.w, av.w);
            fma2(acc2[0][0], a0, bv.x); fma2(acc2[0][1], a0, bv.y);
            fma2(acc2[1][0], a1, bv.x); fma2(acc2[1][1], a1, bv.y);
            fma2(acc2[2][0], a2, bv.x); fma2(acc2[2][1], a2, bv.y);
            fma2(acc2[3][0], a3, bv.x); fma2(acc2[3][1], a3, bv.y);
        }
        __syncthreads();
    }
    const int n = n0 + tx * 4;
    float b0 = bi[n] + bh[n];
    float b1 = bi[n + 1] + bh[n + 1];
    float b2 = bi[n + 2] + bh[n + 2];
    float b3 = bi[n + 3] + bh[n + 3];
#pragma unroll
    for (int i = 0; i < 4; i++) {
        size_t row = (size_t)(m0 + ty * 4 + i);
        float2 c0 = up2(acc2[i][0]);
        float2 c1 = up2(acc2[i][1]);
        float4 v;
        v.x = c0.x + b0; v.y = c0.y + b1;
        v.z = c1.x + b2; v.w = c1.y + b3;
        *(float4*)&outd[row * N + n] = v;
    }
}

// ---------------- big GEMM (layers 1-3): 128x128 tile, single-buffer --------
// OUT[d][m][n] = sum_k (X[m][k]*bns[k]+bnb[k]) * W[d][n][k] + bih+bhh
__global__ void __launch_bounds__(256, 2)
gemm128(const float* __restrict__ X, const float* __restrict__ W,
        const float* __restrict__ bih, const float* __restrict__ bhh,
        const float* __restrict__ bns, const float* __restrict__ bnb,
        float* __restrict__ OUT, int K, int N) {
    __shared__ __align__(16) float As[8][128];
    __shared__ __align__(16) float Bs[8][128];
    __shared__ __align__(16) float ssc[128];
    __shared__ __align__(16) float ssh[128];
    const int tid = threadIdx.x;
    for (int i = tid; i < K; i += 256) { ssc[i] = bns[i]; ssh[i] = bnb[i]; }
    const int d = blockIdx.z;
    const float* Wd = W + (size_t)d * N * K;
    const float* bi = bih + d * N;
    const float* bh = bhh + d * N;
    float* outd = OUT + (size_t)d * (size_t)MROWS * N;
    const int m0 = blockIdx.x * 128, n0 = blockIdx.y * 128;
    const int lrow = tid >> 1, lk = (tid & 1) * 4;
    const float* pX = X + (size_t)(m0 + lrow) * K + lk;
    const float* pW = Wd + (size_t)(n0 + lrow) * K + lk;
    const int tx = tid & 15, ty = tid >> 4;
    unsigned long long acc[8][4] = {};

    float4 xa = *(const float4*)pX;
    float4 wb = *(const float4*)pW;
    __syncthreads();   // ssc/ssh ready

    for (int k0 = 0; k0 < K; k0 += 8) {
        As[lk + 0][lrow] = xa.x * ssc[k0 + lk + 0] + ssh[k0 + lk + 0];
        As[lk + 1][lrow] = xa.y * ssc[k0 + lk + 1] + ssh[k0 + lk + 1];
        As[lk + 2][lrow] = xa.z * ssc[k0 + lk + 2] + ssh[k0 + lk + 2];
        As[lk + 3][lrow] = xa.w * ssc[k0 + lk + 3] + ssh[k0 + lk + 3];
        Bs[lk + 0][lrow] = wb.x;
        Bs[lk + 1][lrow] = wb.y;
        Bs[lk + 2][lrow] = wb.z;
        Bs[lk + 3][lrow] = wb.w;
        __syncthreads();
        if (k0 + 8 < K) {
            pX += 8; pW += 8;
            xa = *(const float4*)pX;
            wb = *(const float4*)pW;
        }
#pragma unroll
        for (int k = 0; k < 8; k++) {
            float4 a0 = *(const float4*)&As[k][ty * 4];
            float4 a1 = *(const float4*)&As[k][ty * 4 + 64];
            ulonglong2 b0 = *(const ulonglong2*)&Bs[k][tx * 4];
            ulonglong2 b1 = *(const ulonglong2*)&Bs[k][tx * 4 + 64];
            unsigned long long am[8];
            am[0] = pk2(a0.x, a0.x); am[1] = pk2(a0.y, a0.y);
            am[2] = pk2(a0.z, a0.z); am[3] = pk2(a0.w, a0.w);
            am[4] = pk2(a1.x, a1.x); am[5] = pk2(a1.y, a1.y);
            am[6] = pk2(a1.z, a1.z); am[7] = pk2(a1.w, a1.w);
#pragma unroll
            for (int i = 0; i < 8; i++) {
                fma2(acc[i][0], am[i], b0.x);
                fma2(acc[i][1], am[i], b0.y);
                fma2(acc[i][2], am[i], b1.x);
                fma2(acc[i][3], am[i], b1.y);
            }
        }
        __syncthreads();
    }

    const int nA = n0 + tx * 4;
    const int nB = nA + 64;
    float bA0 = bi[nA] + bh[nA],         bA1 = bi[nA + 1] + bh[nA + 1];
    float bA2 = bi[nA + 2] + bh[nA + 2], bA3 = bi[nA + 3] + bh[nA + 3];
    float bB0 = bi[nB] + bh[nB],         bB1 = bi[nB + 1] + bh[nB + 1];
    float bB2 = bi[nB + 2] + bh[nB + 2], bB3 = bi[nB + 3] + bh[nB + 3];
#pragma unroll
    for (int i = 0; i < 8; i++) {
        int row = m0 + ((i < 4) ? (ty * 4 + i) : (64 + ty * 4 + i - 4));
        float2 c0 = up2(acc[i][0]);
        float2 c1 = up2(acc[i][1]);
        float2 c2 = up2(acc[i][2]);
        float2 c3 = up2(acc[i][3]);
        float4 v0, v1;
        v0.x = c0.x + bA0; v0.y = c0.y + bA1;
        v0.z = c1.x + bA2; v0.w = c1.y + bA3;
        v1.x = c2.x + bB0; v1.y = c2.y + bB1;
        v1.z = c3.x + bB2; v1.w = c3.y + bB3;
        *(float4*)&outd[(size_t)row * N + nA] = v0;
        *(float4*)&outd[(size_t)row * N + nB] = v1;
    }
}

// ---------------- recurrent scan: smem-gate, one chain per CTA ---------------
// xw: [2][SEQ*BATCH][4H]; whh: [2][4H][H]; out: [SEQ*BATCH][2H], dir offset d*H.
// Fused BN stats: per-chain sum / sumsq written to part/part2 [chain][H].
// H<128: 4-way accumulator split (halved fma2 dependency chain; these scans
// have 0.5-2 warps/SMSP so the serial chain is fully exposed). H=128 keeps
// the proven 2-accumulator code (register budget at 512 threads).
template <int H, int REGK, int D>
__global__ void __launch_bounds__(4 * H)
scan_kernel(const float* __restrict__ xw, const float* __restrict__ whh,
            float* __restrict__ out, float* __restrict__ part,
            float* __restrict__ part2) {
    constexpr int G4 = 4 * H;
    constexpr int HS = H - REGK;
    constexpr int WPAD = 4;
    constexpr bool A4 = (H < 128);   // 4-accumulator dot for small layers
    extern __shared__ __align__(16) float sm[];
    float* h_sh    = sm;          // [H]
    float* gate_sh = sm + H;      // [G4]
    float* w_sh    = gate_sh + G4;

    const int g = threadIdx.x;
    const int chain = blockIdx.x;
    const int d = chain >> 6;
    const int b = chain & 63;

    const float* wrow = whh + ((size_t)d * G4 + g) * H;
    unsigned long long wreg2[REGK / 2];
#pragma unroll
    for (int k = 0; k < REGK; k += 4) {
        float4 w = *(const float4*)(wrow + k);
        wreg2[k / 2]     = pk2(w.x, w.y);
        wreg2[k / 2 + 1] = pk2(w.z, w.w);
    }
    if constexpr (HS > 0) {
        for (int i = g; i < G4 * HS; i += G4) {
            int gg = i / HS, kk = i % HS;
            w_sh[gg * (HS + WPAD) + kk] =
                whh[((size_t)d * G4 + gg) * H + REGK + kk];
        }
    }
    for (int i = g; i < H; i += G4) h_sh[i] = 0.f;
    float c_state = 0.f, s1 = 0.f, s2 = 0.f;
    __syncthreads();

    const bool fwd = (d == 0);
    const long rs = (long)BATCH * G4;
    const long stp = fwd ? rs : -rs;
    const float* p0 = xw + (size_t)d * SEQ * rs +
                      (size_t)(fwd ? 0 : (SEQ - 1)) * rs + (size_t)b * G4 + g;
    float pipe[D];
#pragma unroll
    for (int j = 0; j < D; j++) pipe[j] = p0[(long)j * stp];
    const float* pf = p0 + (long)D * stp;

    const long ors = (long)BATCH * 2 * H;
    const long ostp = fwd ? ors : -ors;
    float* po = out + (size_t)(fwd ? 0 : (SEQ - 1)) * ors +
                (size_t)b * 2 * H + (size_t)d * H;
    const int gi = g / H;
    const float* wp = (HS > 0) ? (w_sh + g * (HS + WPAD)) : nullptr;

    for (int s = 0; s < SEQ; s++) {
        float cur = pipe[0];
#pragma unroll
        for (int j = 0; j < D - 1; j++) pipe[j] = pipe[j + 1];
        pipe[D - 1] = (s + D < SEQ) ? *pf : 0.f;
        pf += stp;

        float acc;
        if constexpr (A4) {
            // REGK in {16,32,64}: divisible by 8, HS == 0.
            unsigned long long a0 = pk2(cur, 0.f), a1 = 0ULL,
                               a2 = 0ULL, a3 = 0ULL;
#pragma unroll
            for (int k = 0; k < REGK; k += 8) {
                ulonglong2 hA = *(const ulonglong2*)(h_sh + k);
                ulonglong2 hB = *(const ulonglong2*)(h_sh + k + 4);
                fma2(a0, hA.x, wreg2[k / 2]);
                fma2(a1, hA.y, wreg2[k / 2 + 1]);
                fma2(a2, hB.x, wreg2[k / 2 + 2]);
                fma2(a3, hB.y, wreg2[k / 2 + 3]);
            }
            float2 f0 = up2(a0), f1 = up2(a1), f2 = up2(a2), f3 = up2(a3);
            acc = ((f0.x + f0.y) + (f1.x + f1.y)) +
                  ((f2.x + f2.y) + (f3.x + f3.y));
        } else {
            unsigned long long a0 = pk2(cur, 0.f), a1 = 0ULL;
#pragma unroll
            for (int k = 0; k < REGK; k += 4) {
                ulonglong2 hv = *(const ulonglong2*)(h_sh + k);
                fma2(a0, hv.x, wreg2[k / 2]);
                fma2(a1, hv.y, wreg2[k / 2 + 1]);
            }
            if constexpr (HS > 0) {
#pragma unroll
                for (int k = 0; k < HS; k += 4) {
                    ulonglong2 hv = *(const ulonglong2*)(h_sh + REGK + k);
                    ulonglong2 wv = *(const ulonglong2*)(wp + k);
                    fma2(a0, hv.x, wv.x);
                    fma2(a1, hv.y, wv.y);
                }
            }
            float2 f0 = up2(a0), f1 = up2(a1);
            acc = (f0.x + f1.x) + (f0.y + f1.y);
        }
        float a = (gi == 2) ? fast_tanh(acc) : fast_sig(acc);
        gate_sh[g] = a;
        __syncthreads();
        if (g < H) {
            float iv = gate_sh[g];
            float fv = gate_sh[H + g];
            float gv = gate_sh[2 * H + g];
            float ov = gate_sh[3 * H + g];
            c_state = fv * c_state + iv * gv;
            float hval = ov * fast_tanh(c_state);
            h_sh[g] = hval;
            po[g] = hval;
            s1 += hval;
            s2 = fmaf(hval, hval, s2);
        }
        __syncthreads();
        po += ostp;
    }
    if (g < H) {
        part [(size_t)chain * H + g] = s1;
        part2[(size_t)chain * H + g] = s2;
    }
}

// ---------------- BN finalize ------------------------------------------------
__global__ void bn_finalize(const float* __restrict__ part,
                            const float* __restrict__ part2,
                            const float* __restrict__ gamma,
                            const float* __restrict__ beta,
                            float* __restrict__ scale, float* __restrict__ shift,
                            int H) {
    int c = threadIdx.x;
    int C = 2 * H;
    if (c >= C) return;
    int d = c / H, h = c % H;
    float s = 0.f, q = 0.f;
    for (int b = 0; b < 64; b++) {
        s += part [((size_t)(d * 64 + b)) * H + h];
        q += part2[((size_t)(d * 64 + b)) * H + h];
    }
    float mean = s / (float)MROWS;
    float var = q / (float)MROWS - mean * mean;
    float sc = gamma[c] * rsqrtf(var + EPSBN);
    scale[c] = sc;
    shift[c] = beta[c] - mean * sc;
}

// ---------------- final FC (BN of layer 3 fused on load) --------------------
__global__ void __launch_bounds__(256)
fc_kernel(const float* __restrict__ X, const float* __restrict__ W,
          const float* __restrict__ bias, const float* __restrict__ bns,
          const float* __restrict__ bnb, float* __restrict__ out) {
    __shared__ __align__(16) float wsh[11 * 256];
    __shared__ __align__(16) float ssc[256];
    __shared__ __align__(16) float ssh[256];
    __shared__ __align__(16) float bsh[16];
    const int tid = threadIdx.x;
    for (int i = tid; i < 11 * 256; i += 256) wsh[i] = W[i];
    if (tid < 11) bsh[tid] = bias[tid];
    ssc[tid] = bns[tid]; ssh[tid] = bnb[tid];
    __syncthreads();
    const int warp = tid >> 5, lane = tid & 31;
    float4 sc0 = *(const float4*)&ssc[lane * 4];
    float4 sc1 = *(const float4*)&ssc[128 + lane * 4];
    float4 sh0 = *(const float4*)&ssh[lane * 4];
    float4 sh1 = *(const float4*)&ssh[128 + lane * 4];
    for (int r = blockIdx.x * 8 + warp; r < MROWS; r += gridDim.x * 8) {
        const float4* xr = (const float4*)(X + (size_t)r * 256);
        float4 v0 = xr[lane];
        float4 v1 = xr[lane + 32];
        v0.x = v0.x * sc0.x + sh0.x; v0.y = v0.y * sc0.y + sh0.y;
        v0.z = v0.z * sc0.z + sh0.z; v0.w = v0.w * sc0.w + sh0.w;
        v1.x = v1.x * sc1.x + sh1.x; v1.y = v1.y * sc1.y + sh1.y;
        v1.z = v1.z * sc1.z + sh1.z; v1.w = v1.w * sc1.w + sh1.w;
        float p[11];
#pragma unroll
        for (int k = 0; k < 11; k++) {
            const float* wk = wsh + k * 256;
            float4 w0 = *(const float4*)(wk + lane * 4);
            float4 w1 = *(const float4*)(wk + 128 + lane * 4);
            p[k] = v0.x * w0.x + v0.y * w0.y + v0.z * w0.z + v0.w * w0.w +
                   v1.x * w1.x + v1.y * w1.y + v1.z * w1.z + v1.w * w1.w;
        }
#pragma unroll
        for (int off = 16; off > 0; off >>= 1)
#pragma unroll
            for (int k = 0; k < 11; k++)
                p[k] += __shfl_xor_sync(0xffffffffu, p[k], off);
        if (lane == 0) {
            int s = r / BATCH, b = r % BATCH;
            float* op = out + ((size_t)b * SEQ + s) * 11;
#pragma unroll
            for (int k = 0; k < 11; k++) op[k] = p[k] + bsh[k];
        }
    }
}

// ---------------- host orchestration ----------------------------------------
extern "C" void kernel_launch(void* const* d_in, const int* in_sizes, int n_in,
                              void* d_out, int out_size) {
    const float* x = (const float*)d_in[0];

    const bool interleaved = (in_sizes[5] == 32);
    const float *wih[4], *whh[4], *bih[4], *bhh[4], *gam[4], *bet[4];
    for (int l = 0; l < 4; l++) {
        if (interleaved) {
            int base = 1 + 6 * l;
            wih[l] = (const float*)d_in[base + 0];
            whh[l] = (const float*)d_in[base + 1];
            bih[l] = (const float*)d_in[base + 2];
            bhh[l] = (const float*)d_in[base + 3];
            gam[l] = (const float*)d_in[base + 4];
            bet[l] = (const float*)d_in[base + 5];
        } else {
            wih[l] = (const float*)d_in[1 + 4 * l];
            whh[l] = (const float*)d_in[2 + 4 * l];
            bih[l] = (const float*)d_in[3 + 4 * l];
            bhh[l] = (const float*)d_in[4 + 4 * l];
            gam[l] = (const float*)d_in[17 + 2 * l];
            bet[l] = (const float*)d_in[18 + 2 * l];
        }
    }
    const float* fcw = (const float*)d_in[25];
    const float* fcb = (const float*)d_in[26];

    float *bufA, *bufB, *xwbuf, *part, *part2, *scale, *shift;
    cudaGetSymbolAddress((void**)&bufA,  g_bufA);
    cudaGetSymbolAddress((void**)&bufB,  g_bufB);
    cudaGetSymbolAddress((void**)&xwbuf, g_xw);
    cudaGetSymbolAddress((void**)&part,  g_part);
    cudaGetSymbolAddress((void**)&part2, g_part2);
    cudaGetSymbolAddress((void**)&scale, g_scale);
    cudaGetSymbolAddress((void**)&shift, g_shift);

    static const int Hs[4] = {16, 32, 64, 128};
    static const int Is[4] = {7, 32, 64, 128};
    const float* prev = nullptr;

    for (int l = 0; l < 4; l++) {
        const int H = Hs[l], K = Is[l], N = 4 * H;

        if (l == 0) {
            dim3 grid(MROWS / 64, N / 64, 2);
            gemm_small<<<grid, 256>>>(x, wih[l], bih[l], bhh[l], xwbuf, K, N);
            // Padding launches (also harmlessly zero the stats scratch):
            // shifts scan_kernel<16> to launch index 3, which is the launch
            // the ncu capture lands on — first-ever scan profile next round.
            pad_zero<<<64, 256>>>(part, 16384);
            pad_zero<<<64, 256>>>(part2, 16384);
        } else {
            dim3 grid(MROWS / 128, N / 128, 2);
            gemm128<<<grid, 256>>>(prev, wih[l], bih[l], bhh[l], scale, shift,
                                   xwbuf, K, N);
        }

        float* o = (l & 1) ? bufB : bufA;
        if (l == 0) {
            size_t smem = (size_t)(16 + 64) * sizeof(float);
            scan_kernel<16, 16, 8><<<128, 64, smem>>>(xwbuf, whh[l], o, part, part2);
        } else if (l == 1) {
            size_t smem = (size_t)(32 + 128) * sizeof(float);
            scan_kernel<32, 32, 8><<<128, 128, smem>>>(xwbuf, whh[l], o, part, part2);
        } else if (l == 2) {
            size_t smem = (size_t)(64 + 256) * sizeof(float);
            scan_kernel<64, 64, 6><<<128, 256, smem>>>(xwbuf, whh[l], o, part, part2);
        } else {
            // H=128: 96 weight cols in regs, 32 in padded smem.
            size_t smem = (size_t)(128 + 512 + 512 * (32 + 4)) * sizeof(float);
            cudaFuncSetAttribute(scan_kernel<128, 96, 4>,
                                 cudaFuncAttributeMaxDynamicSharedMemorySize,
                                 (int)smem);
            scan_kernel<128, 96, 4><<<128, 512, smem>>>(xwbuf, whh[l], o, part, part2);
        }

        bn_finalize<<<1, 256>>>(part, part2, gam[l], bet[l], scale, shift, H);
        prev = o;
    }

    fc_kernel<<<512, 256>>>(prev, fcw, fcb, scale, shift, (float*)d_out);
}

// round 16
// speedup vs baseline: 1.0582x; 1.0582x over previous
#include <cuda_runtime.h>
#include <cstdint>

#define SEQ   2048
#define BATCH 64
#define MROWS (SEQ * BATCH)   // 131072
#define EPSBN 1e-5f

// ---------------- scratch (device globals; no allocations allowed) ----------
__device__ float g_bufA[33554432];    // [MROWS][<=256]
__device__ float g_bufB[33554432];    // [MROWS][<=256]
__device__ float g_xw[134217728];     // [2][MROWS][<=512]
__device__ float g_part [16384];      // [128 chains][<=128]
__device__ float g_part2[16384];
__device__ float g_scale[256];
__device__ float g_shift[256];

// ---------------- f32x2 helpers ---------------------------------------------
__device__ __forceinline__ unsigned long long pk2(float x, float y) {
    unsigned long long r;
    asm("mov.b64 %0, {%1,%2};" : "=l"(r) : "f"(x), "f"(y));
    return r;
}
__device__ __forceinline__ void fma2(unsigned long long& d,
                                     unsigned long long a, unsigned long long b) {
    asm("fma.rn.f32x2 %0, %1, %2, %0;" : "+l"(d) : "l"(a), "l"(b));
}
__device__ __forceinline__ float2 up2(unsigned long long v) {
    float2 f;
    asm("mov.b64 {%0,%1}, %2;" : "=f"(f.x), "=f"(f.y) : "l"(v));
    return f;
}
// MUFU.TANH-based activations: single 16-cyc MUFU instead of EX2+RCP chains.
__device__ __forceinline__ float fast_tanh(float x) {
    float r;
    asm("tanh.approx.f32 %0, %1;" : "=f"(r) : "f"(x));
    return r;
}
__device__ __forceinline__ float fast_sig(float x) {
    float r;
    asm("tanh.approx.f32 %0, %1;" : "=f"(r) : "f"(0.5f * x));
    return fmaf(0.5f, r, 0.5f);
}

// ---------------- padding kernel (also zeroes stats scratch; deterministic) --
__global__ void pad_zero(float* __restrict__ p, int n) {
    int i = blockIdx.x * blockDim.x + threadIdx.x;
    if (i < n) p[i] = 0.f;
}

// ---------------- layer-0 GEMM (N=64, K=7): 64x64 tile ----------------------
__global__ void __launch_bounds__(256)
gemm_small(const float* __restrict__ X, const float* __restrict__ W,
           const float* __restrict__ bih, const float* __restrict__ bhh,
           float* __restrict__ OUT, int K, int N) {
    __shared__ __align__(16) float As[8][64];
    __shared__ __align__(16) float Bs[8][64];
    const int tid = threadIdx.x;
    const int d = blockIdx.z;
    const float* Wd = W + (size_t)d * N * K;
    const float* bi = bih + d * N;
    const float* bh = bhh + d * N;
    float* outd = OUT + (size_t)d * MROWS * N;
    const int m0 = blockIdx.x * 64, n0 = blockIdx.y * 64;
    const int tx = tid & 15, ty = tid >> 4;
    unsigned long long acc2[4][2] = {};
    for (int k0 = 0; k0 < K; k0 += 8) {
#pragma unroll
        for (int it = 0; it < 2; it++) {
            int idx = tid + it * 256;
            int r = idx >> 3, c = idx & 7;
            float xv = 0.f;
            if (k0 + c < K) {
                int m = m0 + r;
                int b = m & 63, s = m >> 6;
                xv = X[((size_t)b * SEQ + s) * 7 + k0 + c];
            }
            As[c][r] = xv;
        }
#pragma unroll
        for (int it = 0; it < 2; it++) {
            int idx = tid + it * 256;
            int n = idx & 63, c = idx >> 6;
            Bs[c][n] = (k0 + c < K) ? Wd[(size_t)(n0 + n) * K + k0 + c] : 0.f;
        }
        __syncthreads();
#pragma unroll
        for (int k = 0; k < 8; k++) {
            float4 av = *(const float4*)&As[k][ty * 4];
            ulonglong2 bv = *(const ulonglong2*)&Bs[k][tx * 4];
            unsigned long long a0 = pk2(av.x, av.x);
            unsigned long long a1 = pk2(av.y, av.y);
            unsigned long long a2 = pk2(av.z, av.z);
            unsigned long long a3 = pk2(av.w, av.w);
            fma2(acc2[0][0], a0, bv.x); fma2(acc2[0][1], a0, bv.y);
            fma2(acc2[1][0], a1, bv.x); fma2(acc2[1][1], a1, bv.y);
            fma2(acc2[2][0], a2, bv.x); fma2(acc2[2][1], a2, bv.y);
            fma2(acc2[3][0], a3, bv.x); fma2(acc2[3][1], a3, bv.y);
        }
        __syncthreads();
    }
    const int n = n0 + tx * 4;
    float b0 = bi[n] + bh[n];
    float b1 = bi[n + 1] + bh[n + 1];
    float b2 = bi[n + 2] + bh[n + 2];
    float b3 = bi[n + 3] + bh[n + 3];
#pragma unroll
    for (int i = 0; i < 4; i++) {
        size_t row = (size_t)(m0 + ty * 4 + i);
        float2 c0 = up2(acc2[i][0]);
        float2 c1 = up2(acc2[i][1]);
        float4 v;
        v.x = c0.x + b0; v.y = c0.y + b1;
        v.z = c1.x + b2; v.w = c1.y + b3;
        *(float4*)&outd[row * N + n] = v;
    }
}

// ---------------- big GEMM (layers 1-3): 128x128 tile, single-buffer --------
// OUT[d][m][n] = sum_k (X[m][k]*bns[k]+bnb[k]) * W[d][n][k] + bih+bhh
__global__ void __launch_bounds__(256, 2)
gemm128(const float* __restrict__ X, const float* __restrict__ W,
        const float* __restrict__ bih, const float* __restrict__ bhh,
        const float* __restrict__ bns, const float* __restrict__ bnb,
        float* __restrict__ OUT, int K, int N) {
    __shared__ __align__(16) float As[8][128];
    __shared__ __align__(16) float Bs[8][128];
    __shared__ __align__(16) float ssc[128];
    __shared__ __align__(16) float ssh[128];
    const int tid = threadIdx.x;
    for (int i = tid; i < K; i += 256) { ssc[i] = bns[i]; ssh[i] = bnb[i]; }
    const int d = blockIdx.z;
    const float* Wd = W + (size_t)d * N * K;
    const float* bi = bih + d * N;
    const float* bh = bhh + d * N;
    float* outd = OUT + (size_t)d * (size_t)MROWS * N;
    const int m0 = blockIdx.x * 128, n0 = blockIdx.y * 128;
    const int lrow = tid >> 1, lk = (tid & 1) * 4;
    const float* pX = X + (size_t)(m0 + lrow) * K + lk;
    const float* pW = Wd + (size_t)(n0 + lrow) * K + lk;
    const int tx = tid & 15, ty = tid >> 4;
    unsigned long long acc[8][4] = {};

    float4 xa = *(const float4*)pX;
    float4 wb = *(const float4*)pW;
    __syncthreads();   // ssc/ssh ready

    for (int k0 = 0; k0 < K; k0 += 8) {
        As[lk + 0][lrow] = xa.x * ssc[k0 + lk + 0] + ssh[k0 + lk + 0];
        As[lk + 1][lrow] = xa.y * ssc[k0 + lk + 1] + ssh[k0 + lk + 1];
        As[lk + 2][lrow] = xa.z * ssc[k0 + lk + 2] + ssh[k0 + lk + 2];
        As[lk + 3][lrow] = xa.w * ssc[k0 + lk + 3] + ssh[k0 + lk + 3];
        Bs[lk + 0][lrow] = wb.x;
        Bs[lk + 1][lrow] = wb.y;
        Bs[lk + 2][lrow] = wb.z;
        Bs[lk + 3][lrow] = wb.w;
        __syncthreads();
        if (k0 + 8 < K) {
            pX += 8; pW += 8;
            xa = *(const float4*)pX;
            wb = *(const float4*)pW;
        }
#pragma unroll
        for (int k = 0; k < 8; k++) {
            float4 a0 = *(const float4*)&As[k][ty * 4];
            float4 a1 = *(const float4*)&As[k][ty * 4 + 64];
            ulonglong2 b0 = *(const ulonglong2*)&Bs[k][tx * 4];
            ulonglong2 b1 = *(const ulonglong2*)&Bs[k][tx * 4 + 64];
            unsigned long long am[8];
            am[0] = pk2(a0.x, a0.x); am[1] = pk2(a0.y, a0.y);
            am[2] = pk2(a0.z, a0.z); am[3] = pk2(a0.w, a0.w);
            am[4] = pk2(a1.x, a1.x); am[5] = pk2(a1.y, a1.y);
            am[6] = pk2(a1.z, a1.z); am[7] = pk2(a1.w, a1.w);
#pragma unroll
            for (int i = 0; i < 8; i++) {
                fma2(acc[i][0], am[i], b0.x);
                fma2(acc[i][1], am[i], b0.y);
                fma2(acc[i][2], am[i], b1.x);
                fma2(acc[i][3], am[i], b1.y);
            }
        }
        __syncthreads();
    }

    const int nA = n0 + tx * 4;
    const int nB = nA + 64;
    float bA0 = bi[nA] + bh[nA],         bA1 = bi[nA + 1] + bh[nA + 1];
    float bA2 = bi[nA + 2] + bh[nA + 2], bA3 = bi[nA + 3] + bh[nA + 3];
    float bB0 = bi[nB] + bh[nB],         bB1 = bi[nB + 1] + bh[nB + 1];
    float bB2 = bi[nB + 2] + bh[nB + 2], bB3 = bi[nB + 3] + bh[nB + 3];
#pragma unroll
    for (int i = 0; i < 8; i++) {
        int row = m0 + ((i < 4) ? (ty * 4 + i) : (64 + ty * 4 + i - 4));
        float2 c0 = up2(acc[i][0]);
        float2 c1 = up2(acc[i][1]);
        float2 c2 = up2(acc[i][2]);
        float2 c3 = up2(acc[i][3]);
        float4 v0, v1;
        v0.x = c0.x + bA0; v0.y = c0.y + bA1;
        v0.z = c1.x + bA2; v0.w = c1.y + bA3;
        v1.x = c2.x + bB0; v1.y = c2.y + bB1;
        v1.z = c3.x + bB2; v1.w = c3.y + bB3;
        *(float4*)&outd[(size_t)row * N + nA] = v0;
        *(float4*)&outd[(size_t)row * N + nB] = v1;
    }
}

// ---------------- recurrent scan: smem-gate, one chain per CTA ---------------
// xw: [2][SEQ*BATCH][4H]; whh: [2][4H][H]; out: [SEQ*BATCH][2H], dir offset d*H.
// Fused BN stats: per-chain sum / sumsq written to part/part2 [chain][H].
template <int H, int REGK, int D>
__global__ void __launch_bounds__(4 * H)
scan_kernel(const float* __restrict__ xw, const float* __restrict__ whh,
            float* __restrict__ out, float* __restrict__ part,
            float* __restrict__ part2) {
    constexpr int G4 = 4 * H;
    constexpr int HS = H - REGK;
    constexpr int WPAD = 4;
    constexpr bool A4 = (H < 128);   // 4-accumulator dot for small layers
    extern __shared__ __align__(16) float sm[];
    float* h_sh    = sm;          // [H]
    float* gate_sh = sm + H;      // [G4]
    float* w_sh    = gate_sh + G4;

    const int g = threadIdx.x;
    const int chain = blockIdx.x;
    const int d = chain >> 6;
    const int b = chain & 63;

    const float* wrow = whh + ((size_t)d * G4 + g) * H;
    unsigned long long wreg2[REGK / 2];
#pragma unroll
    for (int k = 0; k < REGK; k += 4) {
        float4 w = *(const float4*)(wrow + k);
        wreg2[k / 2]     = pk2(w.x, w.y);
        wreg2[k / 2 + 1] = pk2(w.z, w.w);
    }
    if constexpr (HS > 0) {
        for (int i = g; i < G4 * HS; i += G4) {
            int gg = i / HS, kk = i % HS;
            w_sh[gg * (HS + WPAD) + kk] =
                whh[((size_t)d * G4 + gg) * H + REGK + kk];
        }
    }
    for (int i = g; i < H; i += G4) h_sh[i] = 0.f;
    float c_state = 0.f, s1 = 0.f, s2 = 0.f;
    __syncthreads();

    const bool fwd = (d == 0);
    const long rs = (long)BATCH * G4;
    const long stp = fwd ? rs : -rs;
    const float* p0 = xw + (size_t)d * SEQ * rs +
                      (size_t)(fwd ? 0 : (SEQ - 1)) * rs + (size_t)b * G4 + g;
    float pipe[D];
#pragma unroll
    for (int j = 0; j < D; j++) pipe[j] = p0[(long)j * stp];
    const float* pf = p0 + (long)D * stp;

    const long ors = (long)BATCH * 2 * H;
    const long ostp = fwd ? ors : -ors;
    float* po = out + (size_t)(fwd ? 0 : (SEQ - 1)) * ors +
                (size_t)b * 2 * H + (size_t)d * H;
    const int gi = g / H;
    const float* wp = (HS > 0) ? (w_sh + g * (HS + WPAD)) : nullptr;

    for (int s = 0; s < SEQ; s++) {
        float cur = pipe[0];
#pragma unroll
        for (int j = 0; j < D - 1; j++) pipe[j] = pipe[j + 1];
        pipe[D - 1] = (s + D < SEQ) ? *pf : 0.f;
        pf += stp;

        float acc;
        if constexpr (A4) {
            // REGK in {16,32,64}: divisible by 8, HS == 0.
            unsigned long long a0 = pk2(cur, 0.f), a1 = 0ULL,
                               a2 = 0ULL, a3 = 0ULL;
#pragma unroll
            for (int k = 0; k < REGK; k += 8) {
                ulonglong2 hA = *(const ulonglong2*)(h_sh + k);
                ulonglong2 hB = *(const ulonglong2*)(h_sh + k + 4);
                fma2(a0, hA.x, wreg2[k / 2]);
                fma2(a1, hA.y, wreg2[k / 2 + 1]);
                fma2(a2, hB.x, wreg2[k / 2 + 2]);
                fma2(a3, hB.y, wreg2[k / 2 + 3]);
            }
            float2 f0 = up2(a0), f1 = up2(a1), f2 = up2(a2), f3 = up2(a3);
            acc = ((f0.x + f0.y) + (f1.x + f1.y)) +
                  ((f2.x + f2.y) + (f3.x + f3.y));
        } else {
            unsigned long long a0 = pk2(cur, 0.f), a1 = 0ULL;
#pragma unroll
            for (int k = 0; k < REGK; k += 4) {
                ulonglong2 hv = *(const ulonglong2*)(h_sh + k);
                fma2(a0, hv.x, wreg2[k / 2]);
                fma2(a1, hv.y, wreg2[k / 2 + 1]);
            }
            if constexpr (HS > 0) {
#pragma unroll
                for (int k = 0; k < HS; k += 4) {
                    ulonglong2 hv = *(const ulonglong2*)(h_sh + REGK + k);
                    ulonglong2 wv = *(const ulonglong2*)(wp + k);
                    fma2(a0, hv.x, wv.x);
                    fma2(a1, hv.y, wv.y);
                }
            }
            float2 f0 = up2(a0), f1 = up2(a1);
            acc = (f0.x + f1.x) + (f0.y + f1.y);
        }
        float a = (gi == 2) ? fast_tanh(acc) : fast_sig(acc);
        gate_sh[g] = a;
        __syncthreads();
        if (g < H) {
            float iv = gate_sh[g];
            float fv = gate_sh[H + g];
            float gv = gate_sh[2 * H + g];
            float ov = gate_sh[3 * H + g];
            c_state = fv * c_state + iv * gv;
            float hval = ov * fast_tanh(c_state);
            h_sh[g] = hval;
            po[g] = hval;
            s1 += hval;
            s2 = fmaf(hval, hval, s2);
        }
        __syncthreads();
        po += ostp;
    }
    if (g < H) {
        part [(size_t)chain * H + g] = s1;
        part2[(size_t)chain * H + g] = s2;
    }
}

// ---------------- BN finalize ------------------------------------------------
__global__ void bn_finalize(const float* __restrict__ part,
                            const float* __restrict__ part2,
                            const float* __restrict__ gamma,
                            const float* __restrict__ beta,
                            float* __restrict__ scale, float* __restrict__ shift,
                            int H) {
    int c = threadIdx.x;
    int C = 2 * H;
    if (c >= C) return;
    int d = c / H, h = c % H;
    float s = 0.f, q = 0.f;
    for (int b = 0; b < 64; b++) {
        s += part [((size_t)(d * 64 + b)) * H + h];
        q += part2[((size_t)(d * 64 + b)) * H + h];
    }
    float mean = s / (float)MROWS;
    float var = q / (float)MROWS - mean * mean;
    float sc = gamma[c] * rsqrtf(var + EPSBN);
    scale[c] = sc;
    shift[c] = beta[c] - mean * sc;
}

// ---------------- final FC (BN of layer 3 fused on load) --------------------
__global__ void __launch_bounds__(256)
fc_kernel(const float* __restrict__ X, const float* __restrict__ W,
          const float* __restrict__ bias, const float* __restrict__ bns,
          const float* __restrict__ bnb, float* __restrict__ out) {
    __shared__ __align__(16) float wsh[11 * 256];
    __shared__ __align__(16) float ssc[256];
    __shared__ __align__(16) float ssh[256];
    __shared__ __align__(16) float bsh[16];
    const int tid = threadIdx.x;
    for (int i = tid; i < 11 * 256; i += 256) wsh[i] = W[i];
    if (tid < 11) bsh[tid] = bias[tid];
    ssc[tid] = bns[tid]; ssh[tid] = bnb[tid];
    __syncthreads();
    const int warp = tid >> 5, lane = tid & 31;
    float4 sc0 = *(const float4*)&ssc[lane * 4];
    float4 sc1 = *(const float4*)&ssc[128 + lane * 4];
    float4 sh0 = *(const float4*)&ssh[lane * 4];
    float4 sh1 = *(const float4*)&ssh[128 + lane * 4];
    for (int r = blockIdx.x * 8 + warp; r < MROWS; r += gridDim.x * 8) {
        const float4* xr = (const float4*)(X + (size_t)r * 256);
        float4 v0 = xr[lane];
        float4 v1 = xr[lane + 32];
        v0.x = v0.x * sc0.x + sh0.x; v0.y = v0.y * sc0.y + sh0.y;
        v0.z = v0.z * sc0.z + sh0.z; v0.w = v0.w * sc0.w + sh0.w;
        v1.x = v1.x * sc1.x + sh1.x; v1.y = v1.y * sc1.y + sh1.y;
        v1.z = v1.z * sc1.z + sh1.z; v1.w = v1.w * sc1.w + sh1.w;
        float p[11];
#pragma unroll
        for (int k = 0; k < 11; k++) {
            const float* wk = wsh + k * 256;
            float4 w0 = *(const float4*)(wk + lane * 4);
            float4 w1 = *(const float4*)(wk + 128 + lane * 4);
            p[k] = v0.x * w0.x + v0.y * w0.y + v0.z * w0.z + v0.w * w0.w +
                   v1.x * w1.x + v1.y * w1.y + v1.z * w1.z + v1.w * w1.w;
        }
#pragma unroll
        for (int off = 16; off > 0; off >>= 1)
#pragma unroll
            for (int k = 0; k < 11; k++)
                p[k] += __shfl_xor_sync(0xffffffffu, p[k], off);
        if (lane == 0) {
            int s = r / BATCH, b = r % BATCH;
            float* op = out + ((size_t)b * SEQ + s) * 11;
#pragma unroll
            for (int k = 0; k < 11; k++) op[k] = p[k] + bsh[k];
        }
    }
}

// ---------------- host orchestration ----------------------------------------
extern "C" void kernel_launch(void* const* d_in, const int* in_sizes, int n_in,
                              void* d_out, int out_size) {
    const float* x = (const float*)d_in[0];

    const bool interleaved = (in_sizes[5] == 32);
    const float *wih[4], *whh[4], *bih[4], *bhh[4], *gam[4], *bet[4];
    for (int l = 0; l < 4; l++) {
        if (interleaved) {
            int base = 1 + 6 * l;
            wih[l] = (const float*)d_in[base + 0];
            whh[l] = (const float*)d_in[base + 1];
            bih[l] = (const float*)d_in[base + 2];
            bhh[l] = (const float*)d_in[base + 3];
            gam[l] = (const float*)d_in[base + 4];
            bet[l] = (const float*)d_in[base + 5];
        } else {
            wih[l] = (const float*)d_in[1 + 4 * l];
            whh[l] = (const float*)d_in[2 + 4 * l];
            bih[l] = (const float*)d_in[3 + 4 * l];
            bhh[l] = (const float*)d_in[4 + 4 * l];
            gam[l] = (const float*)d_in[17 + 2 * l];
            bet[l] = (const float*)d_in[18 + 2 * l];
        }
    }
    const float* fcw = (const float*)d_in[25];
    const float* fcb = (const float*)d_in[26];

    float *bufA, *bufB, *xwbuf, *part, *part2, *scale, *shift;
    cudaGetSymbolAddress((void**)&bufA,  g_bufA);
    cudaGetSymbolAddress((void**)&bufB,  g_bufB);
    cudaGetSymbolAddress((void**)&xwbuf, g_xw);
    cudaGetSymbolAddress((void**)&part,  g_part);
    cudaGetSymbolAddress((void**)&part2, g_part2);
    cudaGetSymbolAddress((void**)&scale, g_scale);
    cudaGetSymbolAddress((void**)&shift, g_shift);

    static const int Hs[4] = {16, 32, 64, 128};
    static const int Is[4] = {7, 32, 64, 128};
    const float* prev = nullptr;

    for (int l = 0; l < 4; l++) {
        const int H = Hs[l], K = Is[l], N = 4 * H;

        if (l == 0) {
            dim3 grid(MROWS / 64, N / 64, 2);
            gemm_small<<<grid, 256>>>(x, wih[l], bih[l], bhh[l], xwbuf, K, N);
            // Padding launches (also harmlessly zero the stats scratch):
            // keeps scan_kernel<16> at the launch index the ncu capture hits.
            pad_zero<<<64, 256>>>(part, 16384);
            pad_zero<<<64, 256>>>(part2, 16384);
        } else {
            dim3 grid(MROWS / 128, N / 128, 2);
            gemm128<<<grid, 256>>>(prev, wih[l], bih[l], bhh[l], scale, shift,
                                   xwbuf, K, N);
        }

        float* o = (l & 1) ? bufB : bufA;
        if (l == 0) {
            size_t smem = (size_t)(16 + 64) * sizeof(float);
            scan_kernel<16, 16, 8><<<128, 64, smem>>>(xwbuf, whh[l], o, part, part2);
        } else if (l == 1) {
            size_t smem = (size_t)(32 + 128) * sizeof(float);
            scan_kernel<32, 32, 8><<<128, 128, smem>>>(xwbuf, whh[l], o, part, part2);
        } else if (l == 2) {
            size_t smem = (size_t)(64 + 256) * sizeof(float);
            scan_kernel<64, 64, 6><<<128, 256, smem>>>(xwbuf, whh[l], o, part, part2);
        } else {
            // H=128: 96 weight cols in regs, 32 in padded smem.
            size_t smem = (size_t)(128 + 512 + 512 * (32 + 4)) * sizeof(float);
            cudaFuncSetAttribute(scan_kernel<128, 96, 4>,
                                 cudaFuncAttributeMaxDynamicSharedMemorySize,
                                 (int)smem);
            scan_kernel<128, 96, 4><<<128, 512, smem>>>(xwbuf, whh[l], o, part, part2);
        }

        bn_finalize<<<1, 256>>>(part, part2, gam[l], bet[l], scale, shift, H);
        prev = o;
    }

    fc_kernel<<<512, 256>>>(prev, fcw, fcb, scale, shift, (float*)d_out);
}